// round 4
// baseline (speedup 1.0000x reference)
#include <cuda_runtime.h>
#include <cuda_bf16.h>
#include <cstdint>

// ---------------------------------------------------------------------------
// Galerkin linear attention, restructured:
//   [fused] k,v = x @ w_{k,v};  instance-norm rows;  part = k-hat^T v-hat
//   dots = sum_chunks part ; A2 = blockdiag(dots)@w_out ; Wf[b]=w_q@A2[b]/n
//   out[b] = x[b] @ Wf[b] + b_out     (tf32 tensor-core GEMM)
// ---------------------------------------------------------------------------

#define BATCH   4
#define NTOK    8192
#define DIM     256
#define HEADS   8
#define DH      64
#define INNER   512
#define TCH     128                 // tokens per fused chunk
#define NCH     (NTOK / TCH)        // 64

__device__ float g_part[32 * NCH * DH * DH];   // 33.5 MB partial dots
__device__ float g_dots[32 * DH * DH];
__device__ float g_A2[BATCH * INNER * DIM];
__device__ float g_Wf[BATCH * DIM * DIM];

__device__ __forceinline__ uint32_t f2tf32(float f) {
    uint32_t r;
    asm("cvt.rna.tf32.f32 %0, %1;" : "=r"(r) : "f"(f));
    return r;
}

__device__ __forceinline__ void mma_tf32(float* d, const uint32_t* a, const uint32_t* b) {
    asm volatile(
        "mma.sync.aligned.m16n8k8.row.col.f32.tf32.tf32.f32 "
        "{%0,%1,%2,%3}, {%4,%5,%6,%7}, {%8,%9}, {%0,%1,%2,%3};"
        : "+f"(d[0]), "+f"(d[1]), "+f"(d[2]), "+f"(d[3])
        : "r"(a[0]), "r"(a[1]), "r"(a[2]), "r"(a[3]), "r"(b[0]), "r"(b[1]));
}

// ===========================================================================
// Fused: k/v projection (tf32 mma) + in-register instance norm + split-tf32
// partial dots. grid(NCH, 32), 256 threads, dynamic smem.
// ===========================================================================
#define PA 136     // As pitch (8*tg+g conflict-free)
#define PB 72      // Bk/Bv pitch
#define PS 72      // sk/sv pitch
#define FUSED_SMEM ((2*16*PA + 2*2*16*PB) * 4 + 2 * TCH * PS * 4)

__global__ __launch_bounds__(256) void fused_kv_dots(
    const float* __restrict__ x, const float* __restrict__ w_qkv,
    float* __restrict__ part)
{
    extern __shared__ unsigned char smraw[];
    uint32_t* As = (uint32_t*)smraw;           // [2][16][PA]  (x tile, tf32, [k][m])
    uint32_t* Bk = As + 2 * 16 * PA;           // [2][16][PB]
    uint32_t* Bv = Bk + 2 * 16 * PB;
    float* sk = (float*)(Bv + 2 * 16 * PB);    // [TCH][PS] normalized k-hat
    float* sv = sk + TCH * PS;                 // [TCH][PS] normalized v-hat

    const int tid = threadIdx.x;
    const int chunk = blockIdx.x, bh = blockIdx.y;
    const int b = bh >> 3, h = bh & 7;

    const float* xA  = x + ((long long)b * NTOK + (long long)chunk * TCH) * DIM;
    const float* wkp = w_qkv + INNER + h * DH;        // stride 3*INNER
    const float* wvp = w_qkv + 2 * INNER + h * DH;

    const int xRow = tid >> 1, xC = (tid & 1) * 8;    // x: 128 rows x 16 cols
    const int wR = tid >> 4, wC = (tid & 15) * 4;     // w: 16 rows x 64 cols

    const int lane = tid & 31, wid = tid >> 5;
    const int g = lane >> 2, tg = lane & 3;
    const bool isV = (wid >= 4);
    const int warpM = (isV ? wid - 4 : wid) * 32;

    float acc[2][8][4];
    #pragma unroll
    for (int i = 0; i < 2; ++i)
        #pragma unroll
        for (int j = 0; j < 8; ++j)
            #pragma unroll
            for (int c = 0; c < 4; ++c) acc[i][j][c] = 0.f;

    // ---- phase 1: k/v = x @ w (K=256, 16 tiles of 16, double-buffered) ----
    float4 pa0, pa1, pk4, pv4;
    {
        pa0 = *(const float4*)&xA[(long long)xRow * DIM + xC];
        pa1 = *(const float4*)&xA[(long long)xRow * DIM + xC + 4];
        pk4 = *(const float4*)&wkp[(long long)wR * (3 * INNER) + wC];
        pv4 = *(const float4*)&wvp[(long long)wR * (3 * INNER) + wC];
    }
    As[(xC + 0) * PA + xRow] = f2tf32(pa0.x);
    As[(xC + 1) * PA + xRow] = f2tf32(pa0.y);
    As[(xC + 2) * PA + xRow] = f2tf32(pa0.z);
    As[(xC + 3) * PA + xRow] = f2tf32(pa0.w);
    As[(xC + 4) * PA + xRow] = f2tf32(pa1.x);
    As[(xC + 5) * PA + xRow] = f2tf32(pa1.y);
    As[(xC + 6) * PA + xRow] = f2tf32(pa1.z);
    As[(xC + 7) * PA + xRow] = f2tf32(pa1.w);
    Bk[wR * PB + wC + 0] = f2tf32(pk4.x);
    Bk[wR * PB + wC + 1] = f2tf32(pk4.y);
    Bk[wR * PB + wC + 2] = f2tf32(pk4.z);
    Bk[wR * PB + wC + 3] = f2tf32(pk4.w);
    Bv[wR * PB + wC + 0] = f2tf32(pv4.x);
    Bv[wR * PB + wC + 1] = f2tf32(pv4.y);
    Bv[wR * PB + wC + 2] = f2tf32(pv4.z);
    Bv[wR * PB + wC + 3] = f2tf32(pv4.w);
    __syncthreads();

    const uint32_t* Bsel = isV ? Bv : Bk;

    for (int kt = 0; kt < 16; ++kt) {
        const int buf = kt & 1;
        if (kt + 1 < 16) {
            const int k0 = (kt + 1) * 16;
            pa0 = *(const float4*)&xA[(long long)xRow * DIM + k0 + xC];
            pa1 = *(const float4*)&xA[(long long)xRow * DIM + k0 + xC + 4];
            pk4 = *(const float4*)&wkp[(long long)(k0 + wR) * (3 * INNER) + wC];
            pv4 = *(const float4*)&wvp[(long long)(k0 + wR) * (3 * INNER) + wC];
        }

        #pragma unroll
        for (int kk = 0; kk < 16; kk += 8) {
            uint32_t af[2][4], bf[8][2];
            #pragma unroll
            for (int mt = 0; mt < 2; ++mt) {
                const int m = warpM + mt * 16;
                af[mt][0] = As[(buf * 16 + kk + tg) * PA + m + g];
                af[mt][1] = As[(buf * 16 + kk + tg) * PA + m + g + 8];
                af[mt][2] = As[(buf * 16 + kk + tg + 4) * PA + m + g];
                af[mt][3] = As[(buf * 16 + kk + tg + 4) * PA + m + g + 8];
            }
            #pragma unroll
            for (int nt = 0; nt < 8; ++nt) {
                bf[nt][0] = Bsel[(buf * 16 + kk + tg) * PB + nt * 8 + g];
                bf[nt][1] = Bsel[(buf * 16 + kk + tg + 4) * PB + nt * 8 + g];
            }
            #pragma unroll
            for (int mt = 0; mt < 2; ++mt)
                #pragma unroll
                for (int nt = 0; nt < 8; ++nt)
                    mma_tf32(acc[mt][nt], af[mt], bf[nt]);
        }

        if (kt + 1 < 16) {
            const int nb = 1 - buf;
            As[(nb * 16 + xC + 0) * PA + xRow] = f2tf32(pa0.x);
            As[(nb * 16 + xC + 1) * PA + xRow] = f2tf32(pa0.y);
            As[(nb * 16 + xC + 2) * PA + xRow] = f2tf32(pa0.z);
            As[(nb * 16 + xC + 3) * PA + xRow] = f2tf32(pa0.w);
            As[(nb * 16 + xC + 4) * PA + xRow] = f2tf32(pa1.x);
            As[(nb * 16 + xC + 5) * PA + xRow] = f2tf32(pa1.y);
            As[(nb * 16 + xC + 6) * PA + xRow] = f2tf32(pa1.z);
            As[(nb * 16 + xC + 7) * PA + xRow] = f2tf32(pa1.w);
            Bk[(nb * 16 + wR) * PB + wC + 0] = f2tf32(pk4.x);
            Bk[(nb * 16 + wR) * PB + wC + 1] = f2tf32(pk4.y);
            Bk[(nb * 16 + wR) * PB + wC + 2] = f2tf32(pk4.z);
            Bk[(nb * 16 + wR) * PB + wC + 3] = f2tf32(pk4.w);
            Bv[(nb * 16 + wR) * PB + wC + 0] = f2tf32(pv4.x);
            Bv[(nb * 16 + wR) * PB + wC + 1] = f2tf32(pv4.y);
            Bv[(nb * 16 + wR) * PB + wC + 2] = f2tf32(pv4.z);
            Bv[(nb * 16 + wR) * PB + wC + 3] = f2tf32(pv4.w);
            __syncthreads();
        }
    }

    // ---- phase 2: in-register instance norm (rows spread over 4 lanes tg) ----
    float* sdst = isV ? sv : sk;
    #pragma unroll
    for (int mt = 0; mt < 2; ++mt) {
        #pragma unroll
        for (int rr = 0; rr < 2; ++rr) {
            float s = 0.f, q = 0.f;
            #pragma unroll
            for (int nt = 0; nt < 8; ++nt) {
                float v0 = acc[mt][nt][2 * rr], v1 = acc[mt][nt][2 * rr + 1];
                s += v0 + v1;
                q += v0 * v0 + v1 * v1;
            }
            s += __shfl_xor_sync(0xFFFFFFFFu, s, 1);
            s += __shfl_xor_sync(0xFFFFFFFFu, s, 2);
            q += __shfl_xor_sync(0xFFFFFFFFu, q, 1);
            q += __shfl_xor_sync(0xFFFFFFFFu, q, 2);
            const float mu  = s * (1.0f / 64.0f);
            const float var = q * (1.0f / 64.0f) - mu * mu;
            const float inv = rsqrtf(var + 1e-5f);
            const int row = warpM + mt * 16 + g + rr * 8;
            #pragma unroll
            for (int nt = 0; nt < 8; ++nt) {
                float2 o = { (acc[mt][nt][2 * rr] - mu) * inv,
                             (acc[mt][nt][2 * rr + 1] - mu) * inv };
                *(float2*)&sdst[row * PS + nt * 8 + 2 * tg] = o;
            }
        }
    }
    __syncthreads();

    // ---- phase 3: partial dots = k-hat^T @ v-hat  (split tf32: hh+hl+lh) ----
    const int n0 = wid * 8;
    float d[4][4];
    #pragma unroll
    for (int mt = 0; mt < 4; ++mt)
        #pragma unroll
        for (int c = 0; c < 4; ++c) d[mt][c] = 0.f;

    for (int kk = 0; kk < TCH; kk += 8) {
        uint32_t ah[4][4], al[4][4], bhv[2], blv[2];
        #pragma unroll
        for (int mt = 0; mt < 4; ++mt) {
            const int m = mt * 16;
            float f0 = sk[(kk + tg) * PS + m + g];
            float f1 = sk[(kk + tg) * PS + m + g + 8];
            float f2 = sk[(kk + tg + 4) * PS + m + g];
            float f3 = sk[(kk + tg + 4) * PS + m + g + 8];
            ah[mt][0] = f2tf32(f0); al[mt][0] = f2tf32(f0 - __uint_as_float(ah[mt][0]));
            ah[mt][1] = f2tf32(f1); al[mt][1] = f2tf32(f1 - __uint_as_float(ah[mt][1]));
            ah[mt][2] = f2tf32(f2); al[mt][2] = f2tf32(f2 - __uint_as_float(ah[mt][2]));
            ah[mt][3] = f2tf32(f3); al[mt][3] = f2tf32(f3 - __uint_as_float(ah[mt][3]));
        }
        {
            float e0 = sv[(kk + tg) * PS + n0 + g];
            float e1 = sv[(kk + tg + 4) * PS + n0 + g];
            bhv[0] = f2tf32(e0); blv[0] = f2tf32(e0 - __uint_as_float(bhv[0]));
            bhv[1] = f2tf32(e1); blv[1] = f2tf32(e1 - __uint_as_float(bhv[1]));
        }
        #pragma unroll
        for (int mt = 0; mt < 4; ++mt) mma_tf32(d[mt], ah[mt], bhv);
        #pragma unroll
        for (int mt = 0; mt < 4; ++mt) mma_tf32(d[mt], ah[mt], blv);
        #pragma unroll
        for (int mt = 0; mt < 4; ++mt) mma_tf32(d[mt], al[mt], bhv);
    }

    float* op = part + (long long)(bh * NCH + chunk) * (DH * DH);
    #pragma unroll
    for (int mt = 0; mt < 4; ++mt) {
        const int e = mt * 16 + g;
        float2 lo = { d[mt][0], d[mt][1] };
        float2 hi = { d[mt][2], d[mt][3] };
        *(float2*)&op[e * DH + n0 + 2 * tg] = lo;
        *(float2*)&op[(e + 8) * DH + n0 + 2 * tg] = hi;
    }
}

// ===========================================================================
__global__ __launch_bounds__(256) void reduce_dots(
    const float* __restrict__ part, float* __restrict__ dots)
{
    const int bh = blockIdx.x, seg = blockIdx.y;   // grid (32,4)
    #pragma unroll
    for (int j = 0; j < 4; ++j) {
        const int idx = seg * 1024 + j * 256 + threadIdx.x;
        float s = 0.f;
        #pragma unroll 8
        for (int c = 0; c < NCH; ++c)
            s += part[(long long)(bh * NCH + c) * (DH * DH) + idx];
        dots[bh * DH * DH + idx] = s;
    }
}

// A2[b, h*64+e, j] = sum_f dots[b,h][e,f] * w_out[h*64+f, j]; grid (32, 8)
__global__ __launch_bounds__(256) void dots_wout(
    const float* __restrict__ dots, const float* __restrict__ w_out,
    float* __restrict__ A2)
{
    const int bh = blockIdx.x, jt = blockIdx.y;
    const int b = bh >> 3, h = bh & 7;
    __shared__ float sd[DH * DH];
    __shared__ float sw[DH][33];
    for (int i = threadIdx.x; i < DH * DH; i += 256) sd[i] = dots[bh * DH * DH + i];
    for (int i = threadIdx.x; i < DH * 32; i += 256) {
        const int f = i >> 5, j = i & 31;
        sw[f][j] = w_out[(h * DH + f) * DIM + jt * 32 + j];
    }
    __syncthreads();
    for (int idx = threadIdx.x; idx < DH * 32; idx += 256) {
        const int e = idx >> 5, j = idx & 31;
        float s = 0.f;
        #pragma unroll 8
        for (int f = 0; f < DH; ++f) s += sd[e * DH + f] * sw[f][j];
        A2[((long long)b * INNER + h * DH + e) * DIM + jt * 32 + j] = s;
    }
}

// ===========================================================================
// Wf[b] = (1/n) * w_q @ A2[b]  — 64x64-tile fp32 kernel, grid (4,4,BATCH)
// A = w_qkv[:, 0:512] (row stride 3*INNER), B = A2[b] (512x256)
// ===========================================================================
__global__ __launch_bounds__(256) void wf_gemm(
    const float* __restrict__ w_qkv, const float* __restrict__ A2,
    float* __restrict__ Wf)
{
    __shared__ float sA[8][68];   // [kk][m]
    __shared__ float sB[8][68];   // [kk][j]

    const int tid = threadIdx.x;
    const int m0 = blockIdx.y * 64, j0 = blockIdx.x * 64;
    const int b  = blockIdx.z;

    const float* Bb = A2 + (long long)b * INNER * DIM;

    // staging: A-tile (8k x 64m): tid -> m=tid&63, kk=(tid>>6) (2 each)
    const int am = tid & 63, ak = tid >> 6;          // ak in 0..3 (+4)
    // B-tile: tid -> kk=tid>>5 (0..7), j=(tid&31)*2
    const int bk = tid >> 5, bj = (tid & 31) * 2;

    const int ty = (tid >> 4) << 2;                  // 0..60 row base
    const int tx = (tid & 15) << 2;                  // 0..60 col base

    float acc[4][4] = {};

    for (int k0 = 0; k0 < INNER; k0 += 8) {
        sA[ak][am]     = w_qkv[(long long)(m0 + am) * (3 * INNER) + k0 + ak];
        sA[ak + 4][am] = w_qkv[(long long)(m0 + am) * (3 * INNER) + k0 + ak + 4];
        float2 b2 = *(const float2*)&Bb[(long long)(k0 + bk) * DIM + j0 + bj];
        sB[bk][bj] = b2.x;
        sB[bk][bj + 1] = b2.y;
        __syncthreads();
        #pragma unroll
        for (int kk = 0; kk < 8; ++kk) {
            float a[4], bb[4];
            #pragma unroll
            for (int i = 0; i < 4; ++i) a[i] = sA[kk][ty + i];
            #pragma unroll
            for (int j = 0; j < 4; ++j) bb[j] = sB[kk][tx + j];
            #pragma unroll
            for (int i = 0; i < 4; ++i)
                #pragma unroll
                for (int j = 0; j < 4; ++j) acc[i][j] += a[i] * bb[j];
        }
        __syncthreads();
    }

    float* C = Wf + (long long)b * DIM * DIM;
    const float alpha = 1.0f / (float)NTOK;
    #pragma unroll
    for (int i = 0; i < 4; ++i) {
        float4 o = { alpha * acc[i][0], alpha * acc[i][1],
                     alpha * acc[i][2], alpha * acc[i][3] };
        *(float4*)&C[(long long)(m0 + ty + i) * DIM + j0 + tx] = o;
    }
}

// ===========================================================================
// TF32 tensor-core GEMM for the final out = x @ Wf + b_out
// ===========================================================================
__global__ __launch_bounds__(256) void gemm_tf32(
    const float* __restrict__ A, int lda, long long sA,
    const float* __restrict__ B, int ldb, long long sB,
    float* __restrict__ C, int ldc, long long sC,
    int K, const float* __restrict__ bias, float alpha)
{
    __shared__ uint32_t As[2][16][132];
    __shared__ uint32_t Bs[2][16][132];

    const int tid = threadIdx.x;
    const int bx = blockIdx.x, by = blockIdx.y, bz = blockIdx.z;

    A += (long long)bz * sA + (long long)by * 128 * lda;
    B += (long long)bz * sB + (long long)bx * 128;
    C += (long long)bz * sC + (long long)by * 128 * ldc + (long long)bx * 128;

    const int aRow = tid >> 2, aCol = (tid & 3) << 2;
    const int bRow = tid >> 5, bCol = (tid & 31) << 2;

    const int lane = tid & 31, wid = tid >> 5;
    const int warpM = (wid >> 2) * 64;
    const int warpN = (wid & 3) * 32;
    const int g = lane >> 2, tg = lane & 3;

    float acc[4][4][4];
    #pragma unroll
    for (int i = 0; i < 4; ++i)
        #pragma unroll
        for (int j = 0; j < 4; ++j)
            #pragma unroll
            for (int c = 0; c < 4; ++c) acc[i][j][c] = 0.f;

    const int KT = K / 16;

    {
        float4 a0 = *reinterpret_cast<const float4*>(&A[(long long)aRow * lda + aCol]);
        float4 a1 = *reinterpret_cast<const float4*>(&A[(long long)(aRow + 64) * lda + aCol]);
        As[0][aCol + 0][aRow] = f2tf32(a0.x);
        As[0][aCol + 1][aRow] = f2tf32(a0.y);
        As[0][aCol + 2][aRow] = f2tf32(a0.z);
        As[0][aCol + 3][aRow] = f2tf32(a0.w);
        As[0][aCol + 0][aRow + 64] = f2tf32(a1.x);
        As[0][aCol + 1][aRow + 64] = f2tf32(a1.y);
        As[0][aCol + 2][aRow + 64] = f2tf32(a1.z);
        As[0][aCol + 3][aRow + 64] = f2tf32(a1.w);
        float4 b0 = *reinterpret_cast<const float4*>(&B[(long long)bRow * ldb + bCol]);
        float4 b1 = *reinterpret_cast<const float4*>(&B[(long long)(bRow + 8) * ldb + bCol]);
        Bs[0][bRow][bCol + 0] = f2tf32(b0.x);
        Bs[0][bRow][bCol + 1] = f2tf32(b0.y);
        Bs[0][bRow][bCol + 2] = f2tf32(b0.z);
        Bs[0][bRow][bCol + 3] = f2tf32(b0.w);
        Bs[0][bRow + 8][bCol + 0] = f2tf32(b1.x);
        Bs[0][bRow + 8][bCol + 1] = f2tf32(b1.y);
        Bs[0][bRow + 8][bCol + 2] = f2tf32(b1.z);
        Bs[0][bRow + 8][bCol + 3] = f2tf32(b1.w);
    }
    __syncthreads();

    for (int kt = 0; kt < KT; ++kt) {
        const int buf = kt & 1;
        float4 pa0, pa1, pb0, pb1;
        if (kt + 1 < KT) {
            const int k0 = (kt + 1) * 16;
            pa0 = *reinterpret_cast<const float4*>(&A[(long long)aRow * lda + k0 + aCol]);
            pa1 = *reinterpret_cast<const float4*>(&A[(long long)(aRow + 64) * lda + k0 + aCol]);
            pb0 = *reinterpret_cast<const float4*>(&B[(long long)(k0 + bRow) * ldb + bCol]);
            pb1 = *reinterpret_cast<const float4*>(&B[(long long)(k0 + bRow + 8) * ldb + bCol]);
        }

        #pragma unroll
        for (int kk = 0; kk < 16; kk += 8) {
            uint32_t af[4][4], bf[4][2];
            #pragma unroll
            for (int mt = 0; mt < 4; ++mt) {
                const int m = warpM + mt * 16;
                af[mt][0] = As[buf][kk + tg][m + g];
                af[mt][1] = As[buf][kk + tg][m + g + 8];
                af[mt][2] = As[buf][kk + tg + 4][m + g];
                af[mt][3] = As[buf][kk + tg + 4][m + g + 8];
            }
            #pragma unroll
            for (int nt = 0; nt < 4; ++nt) {
                const int n = warpN + nt * 8;
                bf[nt][0] = Bs[buf][kk + tg][n + g];
                bf[nt][1] = Bs[buf][kk + tg + 4][n + g];
            }
            #pragma unroll
            for (int mt = 0; mt < 4; ++mt)
                #pragma unroll
                for (int nt = 0; nt < 4; ++nt)
                    mma_tf32(acc[mt][nt], af[mt], bf[nt]);
        }

        if (kt + 1 < KT) {
            const int nb = 1 - buf;
            As[nb][aCol + 0][aRow] = f2tf32(pa0.x);
            As[nb][aCol + 1][aRow] = f2tf32(pa0.y);
            As[nb][aCol + 2][aRow] = f2tf32(pa0.z);
            As[nb][aCol + 3][aRow] = f2tf32(pa0.w);
            As[nb][aCol + 0][aRow + 64] = f2tf32(pa1.x);
            As[nb][aCol + 1][aRow + 64] = f2tf32(pa1.y);
            As[nb][aCol + 2][aRow + 64] = f2tf32(pa1.z);
            As[nb][aCol + 3][aRow + 64] = f2tf32(pa1.w);
            Bs[nb][bRow][bCol + 0] = f2tf32(pb0.x);
            Bs[nb][bRow][bCol + 1] = f2tf32(pb0.y);
            Bs[nb][bRow][bCol + 2] = f2tf32(pb0.z);
            Bs[nb][bRow][bCol + 3] = f2tf32(pb0.w);
            Bs[nb][bRow + 8][bCol + 0] = f2tf32(pb1.x);
            Bs[nb][bRow + 8][bCol + 1] = f2tf32(pb1.y);
            Bs[nb][bRow + 8][bCol + 2] = f2tf32(pb1.z);
            Bs[nb][bRow + 8][bCol + 3] = f2tf32(pb1.w);
            __syncthreads();
        }
    }

    #pragma unroll
    for (int mt = 0; mt < 4; ++mt) {
        const int r0 = warpM + mt * 16 + g;
        #pragma unroll
        for (int nt = 0; nt < 4; ++nt) {
            const int c0 = warpN + nt * 8 + 2 * tg;
            float bx0 = 0.f, bx1 = 0.f;
            if (bias) {
                const int gcol = blockIdx.x * 128 + c0;
                bx0 = bias[gcol];
                bx1 = bias[gcol + 1];
            }
            float2 lo = { alpha * acc[mt][nt][0] + bx0, alpha * acc[mt][nt][1] + bx1 };
            float2 hi = { alpha * acc[mt][nt][2] + bx0, alpha * acc[mt][nt][3] + bx1 };
            *reinterpret_cast<float2*>(&C[(long long)r0 * ldc + c0]) = lo;
            *reinterpret_cast<float2*>(&C[(long long)(r0 + 8) * ldc + c0]) = hi;
        }
    }
}

// ---------------------------------------------------------------------------
extern "C" void kernel_launch(void* const* d_in, const int* in_sizes, int n_in,
                              void* d_out, int out_size)
{
    const float* x      = (const float*)d_in[0];  // [4, 8192, 256]
    const float* w_qkv  = (const float*)d_in[1];  // [256, 1536]
    const float* w_out  = (const float*)d_in[2];  // [512, 256]
    const float* b_out  = (const float*)d_in[3];  // [256]
    float*       out    = (float*)d_out;          // [4, 8192, 256]

    float *part, *dots, *A2, *Wf;
    cudaGetSymbolAddress((void**)&part, g_part);
    cudaGetSymbolAddress((void**)&dots, g_dots);
    cudaGetSymbolAddress((void**)&A2,   g_A2);
    cudaGetSymbolAddress((void**)&Wf,   g_Wf);

    cudaFuncSetAttribute(fused_kv_dots,
                         cudaFuncAttributeMaxDynamicSharedMemorySize, FUSED_SMEM);

    // 1) fused: k/v projection + instance norm + partial dots
    fused_kv_dots<<<dim3(NCH, 32), 256, FUSED_SMEM>>>(x, w_qkv, part);

    // 2) deterministic chunk reduction
    reduce_dots<<<dim3(32, 4), 256>>>(part, dots);

    // 3) A2 = blockdiag(dots) @ w_out ; Wf[b] = w_q @ A2[b] / n
    dots_wout<<<dim3(32, 8), 256>>>(dots, w_out, A2);
    wf_gemm<<<dim3(4, 4, BATCH), 256>>>(w_qkv, A2, Wf);

    // 4) out[b] = x[b] @ Wf[b] + b_out  (tf32 TC)
    gemm_tf32<<<dim3(DIM / 128, NTOK / 128, BATCH), 256>>>(
        x, DIM, (long long)NTOK * DIM,
        Wf, DIM, (long long)DIM * DIM,
        out, DIM, (long long)NTOK * DIM,
        DIM, b_out, 1.0f);
}

// round 5
// speedup vs baseline: 1.6930x; 1.6930x over previous
#include <cuda_runtime.h>
#include <cuda_bf16.h>
#include <cstdint>

// ---------------------------------------------------------------------------
// Galerkin linear attention, restructured:
//   [fused] k,v = x @ w_{k,v};  instance-norm rows;  part = k-hat^T v-hat
//   dots = sum_chunks part ; A2 = blockdiag(dots)@w_out ; Wf[b]=w_q@A2[b]/n
//   out[b] = x[b] @ Wf[b] + b_out     (tf32 tensor-core GEMM)
// ---------------------------------------------------------------------------

#define BATCH   4
#define NTOK    8192
#define DIM     256
#define HEADS   8
#define DH      64
#define INNER   512
#define TCH     128                 // tokens per fused chunk
#define NCH     (NTOK / TCH)        // 64
#define KSEG    4                   // split-K segments for Wf

__device__ float g_part[32 * NCH * DH * DH];   // 33.5 MB partial dots
__device__ float g_dots[32 * DH * DH];
__device__ float g_A2[BATCH * INNER * DIM];
__device__ float g_WfP[KSEG * BATCH * DIM * DIM];
__device__ float g_Wf[BATCH * DIM * DIM];

__device__ __forceinline__ uint32_t f2tf32(float f) {
    uint32_t r;
    asm("cvt.rna.tf32.f32 %0, %1;" : "=r"(r) : "f"(f));
    return r;
}

__device__ __forceinline__ void mma_tf32(float* d, const uint32_t* a, const uint32_t* b) {
    asm volatile(
        "mma.sync.aligned.m16n8k8.row.col.f32.tf32.tf32.f32 "
        "{%0,%1,%2,%3}, {%4,%5,%6,%7}, {%8,%9}, {%0,%1,%2,%3};"
        : "+f"(d[0]), "+f"(d[1]), "+f"(d[2]), "+f"(d[3])
        : "r"(a[0]), "r"(a[1]), "r"(a[2]), "r"(a[3]), "r"(b[0]), "r"(b[1]));
}

// ===========================================================================
// Fused: k/v projection (tf32 mma) + in-register instance norm + split-tf32
// partial dots. grid(NCH, 32), 256 threads, dynamic smem.
// ===========================================================================
#define PA 136     // As pitch (8*tg+g conflict-free)
#define PB 72      // Bk/Bv pitch
#define PS 72      // sk/sv pitch
#define FUSED_SMEM ((2*16*PA + 2*2*16*PB) * 4 + 2 * TCH * PS * 4)

__global__ __launch_bounds__(256) void fused_kv_dots(
    const float* __restrict__ x, const float* __restrict__ w_qkv,
    float* __restrict__ part)
{
    extern __shared__ unsigned char smraw[];
    uint32_t* As = (uint32_t*)smraw;           // [2][16][PA]  (x tile, tf32, [k][m])
    uint32_t* Bk = As + 2 * 16 * PA;           // [2][16][PB]
    uint32_t* Bv = Bk + 2 * 16 * PB;
    float* sk = (float*)(Bv + 2 * 16 * PB);    // [TCH][PS] normalized k-hat
    float* sv = sk + TCH * PS;                 // [TCH][PS] normalized v-hat

    const int tid = threadIdx.x;
    const int chunk = blockIdx.x, bh = blockIdx.y;
    const int b = bh >> 3, h = bh & 7;

    const float* xA  = x + ((long long)b * NTOK + (long long)chunk * TCH) * DIM;
    const float* wkp = w_qkv + INNER + h * DH;        // stride 3*INNER
    const float* wvp = w_qkv + 2 * INNER + h * DH;

    const int xRow = tid >> 1, xC = (tid & 1) * 8;    // x: 128 rows x 16 cols
    const int wR = tid >> 4, wC = (tid & 15) * 4;     // w: 16 rows x 64 cols

    const int lane = tid & 31, wid = tid >> 5;
    const int g = lane >> 2, tg = lane & 3;
    const bool isV = (wid >= 4);
    const int warpM = (isV ? wid - 4 : wid) * 32;

    float acc[2][8][4];
    #pragma unroll
    for (int i = 0; i < 2; ++i)
        #pragma unroll
        for (int j = 0; j < 8; ++j)
            #pragma unroll
            for (int c = 0; c < 4; ++c) acc[i][j][c] = 0.f;

    // ---- phase 1: k/v = x @ w (K=256, 16 tiles of 16, double-buffered) ----
    float4 pa0, pa1, pk4, pv4;
    {
        pa0 = *(const float4*)&xA[(long long)xRow * DIM + xC];
        pa1 = *(const float4*)&xA[(long long)xRow * DIM + xC + 4];
        pk4 = *(const float4*)&wkp[(long long)wR * (3 * INNER) + wC];
        pv4 = *(const float4*)&wvp[(long long)wR * (3 * INNER) + wC];
    }
    As[(xC + 0) * PA + xRow] = f2tf32(pa0.x);
    As[(xC + 1) * PA + xRow] = f2tf32(pa0.y);
    As[(xC + 2) * PA + xRow] = f2tf32(pa0.z);
    As[(xC + 3) * PA + xRow] = f2tf32(pa0.w);
    As[(xC + 4) * PA + xRow] = f2tf32(pa1.x);
    As[(xC + 5) * PA + xRow] = f2tf32(pa1.y);
    As[(xC + 6) * PA + xRow] = f2tf32(pa1.z);
    As[(xC + 7) * PA + xRow] = f2tf32(pa1.w);
    Bk[wR * PB + wC + 0] = f2tf32(pk4.x);
    Bk[wR * PB + wC + 1] = f2tf32(pk4.y);
    Bk[wR * PB + wC + 2] = f2tf32(pk4.z);
    Bk[wR * PB + wC + 3] = f2tf32(pk4.w);
    Bv[wR * PB + wC + 0] = f2tf32(pv4.x);
    Bv[wR * PB + wC + 1] = f2tf32(pv4.y);
    Bv[wR * PB + wC + 2] = f2tf32(pv4.z);
    Bv[wR * PB + wC + 3] = f2tf32(pv4.w);
    __syncthreads();

    const uint32_t* Bsel = isV ? Bv : Bk;

    for (int kt = 0; kt < 16; ++kt) {
        const int buf = kt & 1;
        if (kt + 1 < 16) {
            const int k0 = (kt + 1) * 16;
            pa0 = *(const float4*)&xA[(long long)xRow * DIM + k0 + xC];
            pa1 = *(const float4*)&xA[(long long)xRow * DIM + k0 + xC + 4];
            pk4 = *(const float4*)&wkp[(long long)(k0 + wR) * (3 * INNER) + wC];
            pv4 = *(const float4*)&wvp[(long long)(k0 + wR) * (3 * INNER) + wC];
        }

        #pragma unroll
        for (int kk = 0; kk < 16; kk += 8) {
            uint32_t af[2][4], bf[8][2];
            #pragma unroll
            for (int mt = 0; mt < 2; ++mt) {
                const int m = warpM + mt * 16;
                af[mt][0] = As[(buf * 16 + kk + tg) * PA + m + g];
                af[mt][1] = As[(buf * 16 + kk + tg) * PA + m + g + 8];
                af[mt][2] = As[(buf * 16 + kk + tg + 4) * PA + m + g];
                af[mt][3] = As[(buf * 16 + kk + tg + 4) * PA + m + g + 8];
            }
            #pragma unroll
            for (int nt = 0; nt < 8; ++nt) {
                bf[nt][0] = Bsel[(buf * 16 + kk + tg) * PB + nt * 8 + g];
                bf[nt][1] = Bsel[(buf * 16 + kk + tg + 4) * PB + nt * 8 + g];
            }
            #pragma unroll
            for (int mt = 0; mt < 2; ++mt)
                #pragma unroll
                for (int nt = 0; nt < 8; ++nt)
                    mma_tf32(acc[mt][nt], af[mt], bf[nt]);
        }

        if (kt + 1 < 16) {
            const int nb = 1 - buf;
            As[(nb * 16 + xC + 0) * PA + xRow] = f2tf32(pa0.x);
            As[(nb * 16 + xC + 1) * PA + xRow] = f2tf32(pa0.y);
            As[(nb * 16 + xC + 2) * PA + xRow] = f2tf32(pa0.z);
            As[(nb * 16 + xC + 3) * PA + xRow] = f2tf32(pa0.w);
            As[(nb * 16 + xC + 4) * PA + xRow] = f2tf32(pa1.x);
            As[(nb * 16 + xC + 5) * PA + xRow] = f2tf32(pa1.y);
            As[(nb * 16 + xC + 6) * PA + xRow] = f2tf32(pa1.z);
            As[(nb * 16 + xC + 7) * PA + xRow] = f2tf32(pa1.w);
            Bk[(nb * 16 + wR) * PB + wC + 0] = f2tf32(pk4.x);
            Bk[(nb * 16 + wR) * PB + wC + 1] = f2tf32(pk4.y);
            Bk[(nb * 16 + wR) * PB + wC + 2] = f2tf32(pk4.z);
            Bk[(nb * 16 + wR) * PB + wC + 3] = f2tf32(pk4.w);
            Bv[(nb * 16 + wR) * PB + wC + 0] = f2tf32(pv4.x);
            Bv[(nb * 16 + wR) * PB + wC + 1] = f2tf32(pv4.y);
            Bv[(nb * 16 + wR) * PB + wC + 2] = f2tf32(pv4.z);
            Bv[(nb * 16 + wR) * PB + wC + 3] = f2tf32(pv4.w);
            __syncthreads();
        }
    }

    // ---- phase 2: in-register instance norm (rows spread over 4 lanes tg) ----
    float* sdst = isV ? sv : sk;
    #pragma unroll
    for (int mt = 0; mt < 2; ++mt) {
        #pragma unroll
        for (int rr = 0; rr < 2; ++rr) {
            float s = 0.f, q = 0.f;
            #pragma unroll
            for (int nt = 0; nt < 8; ++nt) {
                float v0 = acc[mt][nt][2 * rr], v1 = acc[mt][nt][2 * rr + 1];
                s += v0 + v1;
                q += v0 * v0 + v1 * v1;
            }
            s += __shfl_xor_sync(0xFFFFFFFFu, s, 1);
            s += __shfl_xor_sync(0xFFFFFFFFu, s, 2);
            q += __shfl_xor_sync(0xFFFFFFFFu, q, 1);
            q += __shfl_xor_sync(0xFFFFFFFFu, q, 2);
            const float mu  = s * (1.0f / 64.0f);
            const float var = q * (1.0f / 64.0f) - mu * mu;
            const float inv = rsqrtf(var + 1e-5f);
            const int row = warpM + mt * 16 + g + rr * 8;
            #pragma unroll
            for (int nt = 0; nt < 8; ++nt) {
                float2 o = { (acc[mt][nt][2 * rr] - mu) * inv,
                             (acc[mt][nt][2 * rr + 1] - mu) * inv };
                *(float2*)&sdst[row * PS + nt * 8 + 2 * tg] = o;
            }
        }
    }
    __syncthreads();

    // ---- phase 3: partial dots = k-hat^T @ v-hat  (split tf32: hh+hl+lh) ----
    const int n0 = wid * 8;
    float d[4][4];
    #pragma unroll
    for (int mt = 0; mt < 4; ++mt)
        #pragma unroll
        for (int c = 0; c < 4; ++c) d[mt][c] = 0.f;

    for (int kk = 0; kk < TCH; kk += 8) {
        uint32_t ah[4][4], al[4][4], bhv[2], blv[2];
        #pragma unroll
        for (int mt = 0; mt < 4; ++mt) {
            const int m = mt * 16;
            float f0 = sk[(kk + tg) * PS + m + g];
            float f1 = sk[(kk + tg) * PS + m + g + 8];
            float f2 = sk[(kk + tg + 4) * PS + m + g];
            float f3 = sk[(kk + tg + 4) * PS + m + g + 8];
            ah[mt][0] = f2tf32(f0); al[mt][0] = f2tf32(f0 - __uint_as_float(ah[mt][0]));
            ah[mt][1] = f2tf32(f1); al[mt][1] = f2tf32(f1 - __uint_as_float(ah[mt][1]));
            ah[mt][2] = f2tf32(f2); al[mt][2] = f2tf32(f2 - __uint_as_float(ah[mt][2]));
            ah[mt][3] = f2tf32(f3); al[mt][3] = f2tf32(f3 - __uint_as_float(ah[mt][3]));
        }
        {
            float e0 = sv[(kk + tg) * PS + n0 + g];
            float e1 = sv[(kk + tg + 4) * PS + n0 + g];
            bhv[0] = f2tf32(e0); blv[0] = f2tf32(e0 - __uint_as_float(bhv[0]));
            bhv[1] = f2tf32(e1); blv[1] = f2tf32(e1 - __uint_as_float(bhv[1]));
        }
        #pragma unroll
        for (int mt = 0; mt < 4; ++mt) mma_tf32(d[mt], ah[mt], bhv);
        #pragma unroll
        for (int mt = 0; mt < 4; ++mt) mma_tf32(d[mt], ah[mt], blv);
        #pragma unroll
        for (int mt = 0; mt < 4; ++mt) mma_tf32(d[mt], al[mt], bhv);
    }

    float* op = part + (long long)(bh * NCH + chunk) * (DH * DH);
    #pragma unroll
    for (int mt = 0; mt < 4; ++mt) {
        const int e = mt * 16 + g;
        float2 lo = { d[mt][0], d[mt][1] };
        float2 hi = { d[mt][2], d[mt][3] };
        *(float2*)&op[e * DH + n0 + 2 * tg] = lo;
        *(float2*)&op[(e + 8) * DH + n0 + 2 * tg] = hi;
    }
}

// ===========================================================================
__global__ __launch_bounds__(256) void reduce_dots(
    const float* __restrict__ part, float* __restrict__ dots)
{
    const int bh = blockIdx.x, seg = blockIdx.y;   // grid (32,4)
    #pragma unroll
    for (int j = 0; j < 4; ++j) {
        const int idx = seg * 1024 + j * 256 + threadIdx.x;
        float s = 0.f;
        #pragma unroll 8
        for (int c = 0; c < NCH; ++c)
            s += part[(long long)(bh * NCH + c) * (DH * DH) + idx];
        dots[bh * DH * DH + idx] = s;
    }
}

// A2[b, h*64+e, j] = sum_f dots[b,h][e,f] * w_out[h*64+f, j]; grid (32, 8)
__global__ __launch_bounds__(256) void dots_wout(
    const float* __restrict__ dots, const float* __restrict__ w_out,
    float* __restrict__ A2)
{
    const int bh = blockIdx.x, jt = blockIdx.y;
    const int b = bh >> 3, h = bh & 7;
    __shared__ float sd[DH * DH];
    __shared__ float sw[DH][33];
    for (int i = threadIdx.x; i < DH * DH; i += 256) sd[i] = dots[bh * DH * DH + i];
    for (int i = threadIdx.x; i < DH * 32; i += 256) {
        const int f = i >> 5, j = i & 31;
        sw[f][j] = w_out[(h * DH + f) * DIM + jt * 32 + j];
    }
    __syncthreads();
    for (int idx = threadIdx.x; idx < DH * 32; idx += 256) {
        const int e = idx >> 5, j = idx & 31;
        float s = 0.f;
        #pragma unroll 8
        for (int f = 0; f < DH; ++f) s += sd[e * DH + f] * sw[f][j];
        A2[((long long)b * INNER + h * DH + e) * DIM + jt * 32 + j] = s;
    }
}

// ===========================================================================
// WfP[seg][b] = w_q[:, seg*128:(seg+1)*128] @ A2[b][seg*128:(seg+1)*128, :]
// grid (4 jt, 4 mt, BATCH*KSEG) = 256 blocks. 64x64 tile, BK=16, fp32.
// ===========================================================================
__global__ __launch_bounds__(256) void wf_gemm_splitk(
    const float* __restrict__ w_qkv, const float* __restrict__ A2,
    float* __restrict__ WfP)
{
    __shared__ float sA[16][68];   // [kk][m]
    __shared__ float sB[16][68];   // [kk][j]

    const int tid = threadIdx.x;
    const int m0 = blockIdx.y * 64, j0 = blockIdx.x * 64;
    const int bz = blockIdx.z;
    const int b = bz >> 2, seg = bz & 3;
    const int kbase = seg * (INNER / KSEG);          // seg*128

    const float* Bb = A2 + (long long)b * INNER * DIM;

    // A staging: tid -> m=tid>>2 (0..63), kq=(tid&3)*4 ; float4 along k
    const int am = tid >> 2, akq = (tid & 3) * 4;
    // B staging: tid -> kk=tid>>4 (0..15), j=(tid&15)*4 ; float4 along j
    const int bk = tid >> 4, bj = (tid & 15) * 4;

    const int ty = (tid >> 4) << 2;                  // 0..60
    const int tx = (tid & 15) << 2;                  // 0..60

    float acc[4][4] = {};

    for (int k0 = 0; k0 < INNER / KSEG; k0 += 16) {
        float4 a4 = *(const float4*)&w_qkv[(long long)(m0 + am) * (3 * INNER) + kbase + k0 + akq];
        sA[akq + 0][am] = a4.x;
        sA[akq + 1][am] = a4.y;
        sA[akq + 2][am] = a4.z;
        sA[akq + 3][am] = a4.w;
        float4 b4 = *(const float4*)&Bb[(long long)(kbase + k0 + bk) * DIM + j0 + bj];
        *(float4*)&sB[bk][bj] = b4;
        __syncthreads();
        #pragma unroll
        for (int kk = 0; kk < 16; ++kk) {
            float a[4], bb[4];
            #pragma unroll
            for (int i = 0; i < 4; ++i) a[i] = sA[kk][ty + i];
            #pragma unroll
            for (int j = 0; j < 4; ++j) bb[j] = sB[kk][tx + j];
            #pragma unroll
            for (int i = 0; i < 4; ++i)
                #pragma unroll
                for (int j = 0; j < 4; ++j) acc[i][j] += a[i] * bb[j];
        }
        __syncthreads();
    }

    float* C = WfP + ((long long)bz) * DIM * DIM;
    #pragma unroll
    for (int i = 0; i < 4; ++i) {
        float4 o = { acc[i][0], acc[i][1], acc[i][2], acc[i][3] };
        *(float4*)&C[(long long)(m0 + ty + i) * DIM + j0 + tx] = o;
    }
}

// Wf[b] = (1/n) * sum_seg WfP[b*4+seg] ; grid (BATCH*DIM/64, ) hmm: grid 256
__global__ __launch_bounds__(256) void wf_reduce(
    const float* __restrict__ WfP, float* __restrict__ Wf)
{
    const int idx = blockIdx.x * 256 + threadIdx.x;   // over BATCH*DIM*DIM
    const int b = idx / (DIM * DIM);
    const int r = idx % (DIM * DIM);
    float s = 0.f;
    #pragma unroll
    for (int seg = 0; seg < KSEG; ++seg)
        s += WfP[((long long)(b * KSEG + seg)) * DIM * DIM + r];
    Wf[idx] = s * (1.0f / (float)NTOK);
}

// ===========================================================================
// TF32 tensor-core GEMM for the final out = x @ Wf + b_out
// ===========================================================================
__global__ __launch_bounds__(256) void gemm_tf32(
    const float* __restrict__ A, int lda, long long sA,
    const float* __restrict__ B, int ldb, long long sB,
    float* __restrict__ C, int ldc, long long sC,
    int K, const float* __restrict__ bias, float alpha)
{
    __shared__ uint32_t As[2][16][132];
    __shared__ uint32_t Bs[2][16][132];

    const int tid = threadIdx.x;
    const int bx = blockIdx.x, by = blockIdx.y, bz = blockIdx.z;

    A += (long long)bz * sA + (long long)by * 128 * lda;
    B += (long long)bz * sB + (long long)bx * 128;
    C += (long long)bz * sC + (long long)by * 128 * ldc + (long long)bx * 128;

    const int aRow = tid >> 2, aCol = (tid & 3) << 2;
    const int bRow = tid >> 5, bCol = (tid & 31) << 2;

    const int lane = tid & 31, wid = tid >> 5;
    const int warpM = (wid >> 2) * 64;
    const int warpN = (wid & 3) * 32;
    const int g = lane >> 2, tg = lane & 3;

    float acc[4][4][4];
    #pragma unroll
    for (int i = 0; i < 4; ++i)
        #pragma unroll
        for (int j = 0; j < 4; ++j)
            #pragma unroll
            for (int c = 0; c < 4; ++c) acc[i][j][c] = 0.f;

    const int KT = K / 16;

    {
        float4 a0 = *reinterpret_cast<const float4*>(&A[(long long)aRow * lda + aCol]);
        float4 a1 = *reinterpret_cast<const float4*>(&A[(long long)(aRow + 64) * lda + aCol]);
        As[0][aCol + 0][aRow] = f2tf32(a0.x);
        As[0][aCol + 1][aRow] = f2tf32(a0.y);
        As[0][aCol + 2][aRow] = f2tf32(a0.z);
        As[0][aCol + 3][aRow] = f2tf32(a0.w);
        As[0][aCol + 0][aRow + 64] = f2tf32(a1.x);
        As[0][aCol + 1][aRow + 64] = f2tf32(a1.y);
        As[0][aCol + 2][aRow + 64] = f2tf32(a1.z);
        As[0][aCol + 3][aRow + 64] = f2tf32(a1.w);
        float4 b0 = *reinterpret_cast<const float4*>(&B[(long long)bRow * ldb + bCol]);
        float4 b1 = *reinterpret_cast<const float4*>(&B[(long long)(bRow + 8) * ldb + bCol]);
        Bs[0][bRow][bCol + 0] = f2tf32(b0.x);
        Bs[0][bRow][bCol + 1] = f2tf32(b0.y);
        Bs[0][bRow][bCol + 2] = f2tf32(b0.z);
        Bs[0][bRow][bCol + 3] = f2tf32(b0.w);
        Bs[0][bRow + 8][bCol + 0] = f2tf32(b1.x);
        Bs[0][bRow + 8][bCol + 1] = f2tf32(b1.y);
        Bs[0][bRow + 8][bCol + 2] = f2tf32(b1.z);
        Bs[0][bRow + 8][bCol + 3] = f2tf32(b1.w);
    }
    __syncthreads();

    for (int kt = 0; kt < KT; ++kt) {
        const int buf = kt & 1;
        float4 pa0, pa1, pb0, pb1;
        if (kt + 1 < KT) {
            const int k0 = (kt + 1) * 16;
            pa0 = *reinterpret_cast<const float4*>(&A[(long long)aRow * lda + k0 + aCol]);
            pa1 = *reinterpret_cast<const float4*>(&A[(long long)(aRow + 64) * lda + k0 + aCol]);
            pb0 = *reinterpret_cast<const float4*>(&B[(long long)(k0 + bRow) * ldb + bCol]);
            pb1 = *reinterpret_cast<const float4*>(&B[(long long)(k0 + bRow + 8) * ldb + bCol]);
        }

        #pragma unroll
        for (int kk = 0; kk < 16; kk += 8) {
            uint32_t af[4][4], bf[4][2];
            #pragma unroll
            for (int mt = 0; mt < 4; ++mt) {
                const int m = warpM + mt * 16;
                af[mt][0] = As[buf][kk + tg][m + g];
                af[mt][1] = As[buf][kk + tg][m + g + 8];
                af[mt][2] = As[buf][kk + tg + 4][m + g];
                af[mt][3] = As[buf][kk + tg + 4][m + g + 8];
            }
            #pragma unroll
            for (int nt = 0; nt < 4; ++nt) {
                const int n = warpN + nt * 8;
                bf[nt][0] = Bs[buf][kk + tg][n + g];
                bf[nt][1] = Bs[buf][kk + tg + 4][n + g];
            }
            #pragma unroll
            for (int mt = 0; mt < 4; ++mt)
                #pragma unroll
                for (int nt = 0; nt < 4; ++nt)
                    mma_tf32(acc[mt][nt], af[mt], bf[nt]);
        }

        if (kt + 1 < KT) {
            const int nb = 1 - buf;
            As[nb][aCol + 0][aRow] = f2tf32(pa0.x);
            As[nb][aCol + 1][aRow] = f2tf32(pa0.y);
            As[nb][aCol + 2][aRow] = f2tf32(pa0.z);
            As[nb][aCol + 3][aRow] = f2tf32(pa0.w);
            As[nb][aCol + 0][aRow + 64] = f2tf32(pa1.x);
            As[nb][aCol + 1][aRow + 64] = f2tf32(pa1.y);
            As[nb][aCol + 2][aRow + 64] = f2tf32(pa1.z);
            As[nb][aCol + 3][aRow + 64] = f2tf32(pa1.w);
            Bs[nb][bRow][bCol + 0] = f2tf32(pb0.x);
            Bs[nb][bRow][bCol + 1] = f2tf32(pb0.y);
            Bs[nb][bRow][bCol + 2] = f2tf32(pb0.z);
            Bs[nb][bRow][bCol + 3] = f2tf32(pb0.w);
            Bs[nb][bRow + 8][bCol + 0] = f2tf32(pb1.x);
            Bs[nb][bRow + 8][bCol + 1] = f2tf32(pb1.y);
            Bs[nb][bRow + 8][bCol + 2] = f2tf32(pb1.z);
            Bs[nb][bRow + 8][bCol + 3] = f2tf32(pb1.w);
            __syncthreads();
        }
    }

    #pragma unroll
    for (int mt = 0; mt < 4; ++mt) {
        const int r0 = warpM + mt * 16 + g;
        #pragma unroll
        for (int nt = 0; nt < 4; ++nt) {
            const int c0 = warpN + nt * 8 + 2 * tg;
            float bx0 = 0.f, bx1 = 0.f;
            if (bias) {
                const int gcol = blockIdx.x * 128 + c0;
                bx0 = bias[gcol];
                bx1 = bias[gcol + 1];
            }
            float2 lo = { alpha * acc[mt][nt][0] + bx0, alpha * acc[mt][nt][1] + bx1 };
            float2 hi = { alpha * acc[mt][nt][2] + bx0, alpha * acc[mt][nt][3] + bx1 };
            *reinterpret_cast<float2*>(&C[(long long)r0 * ldc + c0]) = lo;
            *reinterpret_cast<float2*>(&C[(long long)(r0 + 8) * ldc + c0]) = hi;
        }
    }
}

// ---------------------------------------------------------------------------
extern "C" void kernel_launch(void* const* d_in, const int* in_sizes, int n_in,
                              void* d_out, int out_size)
{
    const float* x      = (const float*)d_in[0];  // [4, 8192, 256]
    const float* w_qkv  = (const float*)d_in[1];  // [256, 1536]
    const float* w_out  = (const float*)d_in[2];  // [512, 256]
    const float* b_out  = (const float*)d_in[3];  // [256]
    float*       out    = (float*)d_out;          // [4, 8192, 256]

    float *part, *dots, *A2, *WfP, *Wf;
    cudaGetSymbolAddress((void**)&part, g_part);
    cudaGetSymbolAddress((void**)&dots, g_dots);
    cudaGetSymbolAddress((void**)&A2,   g_A2);
    cudaGetSymbolAddress((void**)&WfP,  g_WfP);
    cudaGetSymbolAddress((void**)&Wf,   g_Wf);

    cudaFuncSetAttribute(fused_kv_dots,
                         cudaFuncAttributeMaxDynamicSharedMemorySize, FUSED_SMEM);

    // 1) fused: k/v projection + instance norm + partial dots
    fused_kv_dots<<<dim3(NCH, 32), 256, FUSED_SMEM>>>(x, w_qkv, part);

    // 2) deterministic chunk reduction
    reduce_dots<<<dim3(32, 4), 256>>>(part, dots);

    // 3) A2 = blockdiag(dots) @ w_out ; Wf[b] = w_q @ A2[b] / n (split-K)
    dots_wout<<<dim3(32, 8), 256>>>(dots, w_out, A2);
    wf_gemm_splitk<<<dim3(4, 4, BATCH * KSEG), 256>>>(w_qkv, A2, WfP);
    wf_reduce<<<(BATCH * DIM * DIM) / 256, 256>>>(WfP, Wf);

    // 4) out[b] = x[b] @ Wf[b] + b_out  (tf32 TC)
    gemm_tf32<<<dim3(DIM / 128, NTOK / 128, BATCH), 256>>>(
        x, DIM, (long long)NTOK * DIM,
        Wf, DIM, (long long)DIM * DIM,
        out, DIM, (long long)NTOK * DIM,
        DIM, b_out, 1.0f);
}

// round 7
// speedup vs baseline: 1.8364x; 1.0847x over previous
#include <cuda_runtime.h>
#include <cuda_bf16.h>
#include <cstdint>

// ---------------------------------------------------------------------------
// Galerkin linear attention, restructured:
//   [fused] k,v = x @ w_{k,v};  instance-norm rows;  part = k-hat^T v-hat
//   dots = sum_chunks part ; A2 = blockdiag(dots)@w_out ; Wf[b]=w_q@A2[b]/n
//   out[b] = x[b] @ Wf[b] + b_out     (tf32 tensor-core GEMM)
// ---------------------------------------------------------------------------

#define BATCH   4
#define NTOK    8192
#define DIM     256
#define HEADS   8
#define DH      64
#define INNER   512
#define TCH     128                 // tokens per fused chunk
#define NCH     (NTOK / TCH)        // 64
#define KSEG    4                   // split-K segments for Wf

__device__ float g_part[32 * NCH * DH * DH];   // 33.5 MB partial dots
__device__ float g_dots[32 * DH * DH];
__device__ float g_A2[BATCH * INNER * DIM];
__device__ float g_WfP[KSEG * BATCH * DIM * DIM];
__device__ float g_Wf[BATCH * DIM * DIM];

__device__ __forceinline__ uint32_t f2tf32(float f) {
    uint32_t r;
    asm("cvt.rna.tf32.f32 %0, %1;" : "=r"(r) : "f"(f));
    return r;
}

// round-to-nearest tf32 split via integer ops (ALU pipe, not convert pipe)
__device__ __forceinline__ void split_tf32(float f, uint32_t& hi, uint32_t& lo) {
    uint32_t b = __float_as_uint(f);
    hi = (b + 0x1000u) & 0xFFFFE000u;
    lo = __float_as_uint(f - __uint_as_float(hi));
}

__device__ __forceinline__ void mma_tf32(float* d, const uint32_t* a, const uint32_t* b) {
    asm volatile(
        "mma.sync.aligned.m16n8k8.row.col.f32.tf32.tf32.f32 "
        "{%0,%1,%2,%3}, {%4,%5,%6,%7}, {%8,%9}, {%0,%1,%2,%3};"
        : "+f"(d[0]), "+f"(d[1]), "+f"(d[2]), "+f"(d[3])
        : "r"(a[0]), "r"(a[1]), "r"(a[2]), "r"(a[3]), "r"(b[0]), "r"(b[1]));
}

// ===========================================================================
// Fused: k/v projection (tf32 mma) + in-register instance norm + split-tf32
// partial dots. grid(NCH, 32), 256 threads, dynamic smem.
// smem layout: staging (As|Bk|Bv, 35840 B) is ALIASED by sk/sv (73728 B);
// staging is dead after phase 1 (guarded by __syncthreads).
// ===========================================================================
#define PA 136     // As pitch (8*tg+g conflict-free)
#define PB 72      // Bk/Bv pitch
#define PS 72      // sk/sv pitch
#define FUSED_SMEM (2 * TCH * PS * 4)   // 73728 B (>= staging 35840 B)

__global__ __launch_bounds__(256) void fused_kv_dots(
    const float* __restrict__ x, const float* __restrict__ w_qkv,
    float* __restrict__ part)
{
    extern __shared__ unsigned char smraw[];
    uint32_t* As = (uint32_t*)smraw;           // [2][16][PA]  (x tile, tf32, [k][m])
    uint32_t* Bk = As + 2 * 16 * PA;           // [2][16][PB]
    uint32_t* Bv = Bk + 2 * 16 * PB;
    float* sk = (float*)smraw;                 // [TCH][PS] (aliases staging, used later)
    float* sv = sk + TCH * PS;

    const int tid = threadIdx.x;
    const int chunk = blockIdx.x, bh = blockIdx.y;
    const int b = bh >> 3, h = bh & 7;

    const float* xA  = x + ((long long)b * NTOK + (long long)chunk * TCH) * DIM;
    const float* wkp = w_qkv + INNER + h * DH;        // stride 3*INNER
    const float* wvp = w_qkv + 2 * INNER + h * DH;

    const int xRow = tid >> 1, xC = (tid & 1) * 8;    // x: 128 rows x 16 cols
    const int wR = tid >> 4, wC = (tid & 15) * 4;     // w: 16 rows x 64 cols

    const int lane = tid & 31, wid = tid >> 5;
    const int g = lane >> 2, tg = lane & 3;
    const bool isV = (wid >= 4);
    const int warpM = (isV ? wid - 4 : wid) * 32;

    float acc[2][8][4];
    #pragma unroll
    for (int i = 0; i < 2; ++i)
        #pragma unroll
        for (int j = 0; j < 8; ++j)
            #pragma unroll
            for (int c = 0; c < 4; ++c) acc[i][j][c] = 0.f;

    // ---- phase 1: k/v = x @ w (K=256, 16 tiles of 16, double-buffered) ----
    float4 pa0, pa1, pk4, pv4;
    {
        pa0 = *(const float4*)&xA[(long long)xRow * DIM + xC];
        pa1 = *(const float4*)&xA[(long long)xRow * DIM + xC + 4];
        pk4 = *(const float4*)&wkp[(long long)wR * (3 * INNER) + wC];
        pv4 = *(const float4*)&wvp[(long long)wR * (3 * INNER) + wC];
    }
    As[(xC + 0) * PA + xRow] = f2tf32(pa0.x);
    As[(xC + 1) * PA + xRow] = f2tf32(pa0.y);
    As[(xC + 2) * PA + xRow] = f2tf32(pa0.z);
    As[(xC + 3) * PA + xRow] = f2tf32(pa0.w);
    As[(xC + 4) * PA + xRow] = f2tf32(pa1.x);
    As[(xC + 5) * PA + xRow] = f2tf32(pa1.y);
    As[(xC + 6) * PA + xRow] = f2tf32(pa1.z);
    As[(xC + 7) * PA + xRow] = f2tf32(pa1.w);
    {
        uint4 uk = { f2tf32(pk4.x), f2tf32(pk4.y), f2tf32(pk4.z), f2tf32(pk4.w) };
        uint4 uv = { f2tf32(pv4.x), f2tf32(pv4.y), f2tf32(pv4.z), f2tf32(pv4.w) };
        *(uint4*)&Bk[wR * PB + wC] = uk;
        *(uint4*)&Bv[wR * PB + wC] = uv;
    }
    __syncthreads();

    const uint32_t* Bsel = isV ? Bv : Bk;

    for (int kt = 0; kt < 16; ++kt) {
        const int buf = kt & 1;
        if (kt + 1 < 16) {
            const int k0 = (kt + 1) * 16;
            pa0 = *(const float4*)&xA[(long long)xRow * DIM + k0 + xC];
            pa1 = *(const float4*)&xA[(long long)xRow * DIM + k0 + xC + 4];
            pk4 = *(const float4*)&wkp[(long long)(k0 + wR) * (3 * INNER) + wC];
            pv4 = *(const float4*)&wvp[(long long)(k0 + wR) * (3 * INNER) + wC];
        }

        #pragma unroll
        for (int kk = 0; kk < 16; kk += 8) {
            uint32_t af[2][4], bf[8][2];
            #pragma unroll
            for (int mt = 0; mt < 2; ++mt) {
                const int m = warpM + mt * 16;
                af[mt][0] = As[(buf * 16 + kk + tg) * PA + m + g];
                af[mt][1] = As[(buf * 16 + kk + tg) * PA + m + g + 8];
                af[mt][2] = As[(buf * 16 + kk + tg + 4) * PA + m + g];
                af[mt][3] = As[(buf * 16 + kk + tg + 4) * PA + m + g + 8];
            }
            #pragma unroll
            for (int nt = 0; nt < 8; ++nt) {
                bf[nt][0] = Bsel[(buf * 16 + kk + tg) * PB + nt * 8 + g];
                bf[nt][1] = Bsel[(buf * 16 + kk + tg + 4) * PB + nt * 8 + g];
            }
            #pragma unroll
            for (int mt = 0; mt < 2; ++mt)
                #pragma unroll
                for (int nt = 0; nt < 8; ++nt)
                    mma_tf32(acc[mt][nt], af[mt], bf[nt]);
        }

        if (kt + 1 < 16) {
            const int nb = 1 - buf;
            As[(nb * 16 + xC + 0) * PA + xRow] = f2tf32(pa0.x);
            As[(nb * 16 + xC + 1) * PA + xRow] = f2tf32(pa0.y);
            As[(nb * 16 + xC + 2) * PA + xRow] = f2tf32(pa0.z);
            As[(nb * 16 + xC + 3) * PA + xRow] = f2tf32(pa0.w);
            As[(nb * 16 + xC + 4) * PA + xRow] = f2tf32(pa1.x);
            As[(nb * 16 + xC + 5) * PA + xRow] = f2tf32(pa1.y);
            As[(nb * 16 + xC + 6) * PA + xRow] = f2tf32(pa1.z);
            As[(nb * 16 + xC + 7) * PA + xRow] = f2tf32(pa1.w);
            uint4 uk = { f2tf32(pk4.x), f2tf32(pk4.y), f2tf32(pk4.z), f2tf32(pk4.w) };
            uint4 uv = { f2tf32(pv4.x), f2tf32(pv4.y), f2tf32(pv4.z), f2tf32(pv4.w) };
            *(uint4*)&Bk[(nb * 16 + wR) * PB + wC] = uk;
            *(uint4*)&Bv[(nb * 16 + wR) * PB + wC] = uv;
            __syncthreads();
        }
    }

    // staging region is about to be overwritten by sk/sv — all warps must be
    // done with their last mma's smem reads first.
    __syncthreads();

    // ---- phase 2: in-register instance norm (rows spread over 4 lanes tg) ----
    float* sdst = isV ? sv : sk;
    #pragma unroll
    for (int mt = 0; mt < 2; ++mt) {
        #pragma unroll
        for (int rr = 0; rr < 2; ++rr) {
            float s = 0.f, q = 0.f;
            #pragma unroll
            for (int nt = 0; nt < 8; ++nt) {
                float v0 = acc[mt][nt][2 * rr], v1 = acc[mt][nt][2 * rr + 1];
                s += v0 + v1;
                q += v0 * v0 + v1 * v1;
            }
            s += __shfl_xor_sync(0xFFFFFFFFu, s, 1);
            s += __shfl_xor_sync(0xFFFFFFFFu, s, 2);
            q += __shfl_xor_sync(0xFFFFFFFFu, q, 1);
            q += __shfl_xor_sync(0xFFFFFFFFu, q, 2);
            const float mu  = s * (1.0f / 64.0f);
            const float var = q * (1.0f / 64.0f) - mu * mu;
            const float inv = rsqrtf(var + 1e-5f);
            const int row = warpM + mt * 16 + g + rr * 8;
            #pragma unroll
            for (int nt = 0; nt < 8; ++nt) {
                float2 o = { (acc[mt][nt][2 * rr] - mu) * inv,
                             (acc[mt][nt][2 * rr + 1] - mu) * inv };
                *(float2*)&sdst[row * PS + nt * 8 + 2 * tg] = o;
            }
        }
    }
    __syncthreads();

    // ---- phase 3: partial dots = k-hat^T @ v-hat  (split tf32: hh+hl+lh) ----
    const int n0 = wid * 8;
    float d[4][4];
    #pragma unroll
    for (int mt = 0; mt < 4; ++mt)
        #pragma unroll
        for (int c = 0; c < 4; ++c) d[mt][c] = 0.f;

    for (int kk = 0; kk < TCH; kk += 8) {
        uint32_t ah[4][4], al[4][4], bhv[2], blv[2];
        #pragma unroll
        for (int mt = 0; mt < 4; ++mt) {
            const int m = mt * 16;
            float f0 = sk[(kk + tg) * PS + m + g];
            float f1 = sk[(kk + tg) * PS + m + g + 8];
            float f2 = sk[(kk + tg + 4) * PS + m + g];
            float f3 = sk[(kk + tg + 4) * PS + m + g + 8];
            split_tf32(f0, ah[mt][0], al[mt][0]);
            split_tf32(f1, ah[mt][1], al[mt][1]);
            split_tf32(f2, ah[mt][2], al[mt][2]);
            split_tf32(f3, ah[mt][3], al[mt][3]);
        }
        {
            float e0 = sv[(kk + tg) * PS + n0 + g];
            float e1 = sv[(kk + tg + 4) * PS + n0 + g];
            split_tf32(e0, bhv[0], blv[0]);
            split_tf32(e1, bhv[1], blv[1]);
        }
        #pragma unroll
        for (int mt = 0; mt < 4; ++mt) mma_tf32(d[mt], ah[mt], bhv);
        #pragma unroll
        for (int mt = 0; mt < 4; ++mt) mma_tf32(d[mt], ah[mt], blv);
        #pragma unroll
        for (int mt = 0; mt < 4; ++mt) mma_tf32(d[mt], al[mt], bhv);
    }

    float* op = part + (long long)(bh * NCH + chunk) * (DH * DH);
    #pragma unroll
    for (int mt = 0; mt < 4; ++mt) {
        const int e = mt * 16 + g;
        float2 lo = { d[mt][0], d[mt][1] };
        float2 hi = { d[mt][2], d[mt][3] };
        *(float2*)&op[e * DH + n0 + 2 * tg] = lo;
        *(float2*)&op[(e + 8) * DH + n0 + 2 * tg] = hi;
    }
}

// ===========================================================================
__global__ __launch_bounds__(256) void reduce_dots(
    const float* __restrict__ part, float* __restrict__ dots)
{
    const int bh = blockIdx.x, seg = blockIdx.y;   // grid (32,4)
    #pragma unroll
    for (int j = 0; j < 4; ++j) {
        const int idx = seg * 1024 + j * 256 + threadIdx.x;
        float s = 0.f;
        #pragma unroll 8
        for (int c = 0; c < NCH; ++c)
            s += part[(long long)(bh * NCH + c) * (DH * DH) + idx];
        dots[bh * DH * DH + idx] = s;
    }
}

// A2[b, h*64+e, j] = sum_f dots[b,h][e,f] * w_out[h*64+f, j]; grid (32, 8)
__global__ __launch_bounds__(256) void dots_wout(
    const float* __restrict__ dots, const float* __restrict__ w_out,
    float* __restrict__ A2)
{
    const int bh = blockIdx.x, jt = blockIdx.y;
    const int b = bh >> 3, h = bh & 7;
    __shared__ float sd[DH * DH];
    __shared__ float sw[DH][33];
    for (int i = threadIdx.x; i < DH * DH; i += 256) sd[i] = dots[bh * DH * DH + i];
    for (int i = threadIdx.x; i < DH * 32; i += 256) {
        const int f = i >> 5, j = i & 31;
        sw[f][j] = w_out[(h * DH + f) * DIM + jt * 32 + j];
    }
    __syncthreads();
    for (int idx = threadIdx.x; idx < DH * 32; idx += 256) {
        const int e = idx >> 5, j = idx & 31;
        float s = 0.f;
        #pragma unroll 8
        for (int f = 0; f < DH; ++f) s += sd[e * DH + f] * sw[f][j];
        A2[((long long)b * INNER + h * DH + e) * DIM + jt * 32 + j] = s;
    }
}

// ===========================================================================
// WfP[seg][b] = w_q[:, seg*128:(seg+1)*128] @ A2[b][seg*128:(seg+1)*128, :]
// grid (4 jt, 4 mt, BATCH*KSEG) = 256 blocks. 64x64 tile, BK=16, fp32.
// ===========================================================================
__global__ __launch_bounds__(256) void wf_gemm_splitk(
    const float* __restrict__ w_qkv, const float* __restrict__ A2,
    float* __restrict__ WfP)
{
    __shared__ float sA[16][68];   // [kk][m]
    __shared__ float sB[16][68];   // [kk][j]

    const int tid = threadIdx.x;
    const int m0 = blockIdx.y * 64, j0 = blockIdx.x * 64;
    const int bz = blockIdx.z;
    const int b = bz >> 2, seg = bz & 3;
    const int kbase = seg * (INNER / KSEG);          // seg*128

    const float* Bb = A2 + (long long)b * INNER * DIM;

    const int am = tid >> 2, akq = (tid & 3) * 4;
    const int bk = tid >> 4, bj = (tid & 15) * 4;
    const int ty = (tid >> 4) << 2;
    const int tx = (tid & 15) << 2;

    float acc[4][4] = {};

    for (int k0 = 0; k0 < INNER / KSEG; k0 += 16) {
        float4 a4 = *(const float4*)&w_qkv[(long long)(m0 + am) * (3 * INNER) + kbase + k0 + akq];
        sA[akq + 0][am] = a4.x;
        sA[akq + 1][am] = a4.y;
        sA[akq + 2][am] = a4.z;
        sA[akq + 3][am] = a4.w;
        float4 b4 = *(const float4*)&Bb[(long long)(kbase + k0 + bk) * DIM + j0 + bj];
        *(float4*)&sB[bk][bj] = b4;
        __syncthreads();
        #pragma unroll
        for (int kk = 0; kk < 16; ++kk) {
            float a[4], bb[4];
            #pragma unroll
            for (int i = 0; i < 4; ++i) a[i] = sA[kk][ty + i];
            #pragma unroll
            for (int j = 0; j < 4; ++j) bb[j] = sB[kk][tx + j];
            #pragma unroll
            for (int i = 0; i < 4; ++i)
                #pragma unroll
                for (int j = 0; j < 4; ++j) acc[i][j] += a[i] * bb[j];
        }
        __syncthreads();
    }

    float* C = WfP + ((long long)bz) * DIM * DIM;
    #pragma unroll
    for (int i = 0; i < 4; ++i) {
        float4 o = { acc[i][0], acc[i][1], acc[i][2], acc[i][3] };
        *(float4*)&C[(long long)(m0 + ty + i) * DIM + j0 + tx] = o;
    }
}

__global__ __launch_bounds__(256) void wf_reduce(
    const float* __restrict__ WfP, float* __restrict__ Wf)
{
    const int idx = blockIdx.x * 256 + threadIdx.x;   // over BATCH*DIM*DIM
    const int b = idx / (DIM * DIM);
    const int r = idx % (DIM * DIM);
    float s = 0.f;
    #pragma unroll
    for (int seg = 0; seg < KSEG; ++seg)
        s += WfP[((long long)(b * KSEG + seg)) * DIM * DIM + r];
    Wf[idx] = s * (1.0f / (float)NTOK);
}

// ===========================================================================
// TF32 tensor-core GEMM for the final out = x @ Wf + b_out
// ===========================================================================
__global__ __launch_bounds__(256) void gemm_tf32(
    const float* __restrict__ A, int lda, long long sA,
    const float* __restrict__ B, int ldb, long long sB,
    float* __restrict__ C, int ldc, long long sC,
    int K, const float* __restrict__ bias, float alpha)
{
    __shared__ uint32_t As[2][16][132];
    __shared__ uint32_t Bs[2][16][132];

    const int tid = threadIdx.x;
    const int bx = blockIdx.x, by = blockIdx.y, bz = blockIdx.z;

    A += (long long)bz * sA + (long long)by * 128 * lda;
    B += (long long)bz * sB + (long long)bx * 128;
    C += (long long)bz * sC + (long long)by * 128 * ldc + (long long)bx * 128;

    const int aRow = tid >> 2, aCol = (tid & 3) << 2;
    const int bRow = tid >> 5, bCol = (tid & 31) << 2;

    const int lane = tid & 31, wid = tid >> 5;
    const int warpM = (wid >> 2) * 64;
    const int warpN = (wid & 3) * 32;
    const int g = lane >> 2, tg = lane & 3;

    float acc[4][4][4];
    #pragma unroll
    for (int i = 0; i < 4; ++i)
        #pragma unroll
        for (int j = 0; j < 4; ++j)
            #pragma unroll
            for (int c = 0; c < 4; ++c) acc[i][j][c] = 0.f;

    const int KT = K / 16;

    {
        float4 a0 = *reinterpret_cast<const float4*>(&A[(long long)aRow * lda + aCol]);
        float4 a1 = *reinterpret_cast<const float4*>(&A[(long long)(aRow + 64) * lda + aCol]);
        As[0][aCol + 0][aRow] = f2tf32(a0.x);
        As[0][aCol + 1][aRow] = f2tf32(a0.y);
        As[0][aCol + 2][aRow] = f2tf32(a0.z);
        As[0][aCol + 3][aRow] = f2tf32(a0.w);
        As[0][aCol + 0][aRow + 64] = f2tf32(a1.x);
        As[0][aCol + 1][aRow + 64] = f2tf32(a1.y);
        As[0][aCol + 2][aRow + 64] = f2tf32(a1.z);
        As[0][aCol + 3][aRow + 64] = f2tf32(a1.w);
        float4 b0 = *reinterpret_cast<const float4*>(&B[(long long)bRow * ldb + bCol]);
        float4 b1 = *reinterpret_cast<const float4*>(&B[(long long)(bRow + 8) * ldb + bCol]);
        uint4 u0 = { f2tf32(b0.x), f2tf32(b0.y), f2tf32(b0.z), f2tf32(b0.w) };
        uint4 u1 = { f2tf32(b1.x), f2tf32(b1.y), f2tf32(b1.z), f2tf32(b1.w) };
        *(uint4*)&Bs[0][bRow][bCol] = u0;
        *(uint4*)&Bs[0][bRow + 8][bCol] = u1;
    }
    __syncthreads();

    for (int kt = 0; kt < KT; ++kt) {
        const int buf = kt & 1;
        float4 pa0, pa1, pb0, pb1;
        if (kt + 1 < KT) {
            const int k0 = (kt + 1) * 16;
            pa0 = *reinterpret_cast<const float4*>(&A[(long long)aRow * lda + k0 + aCol]);
            pa1 = *reinterpret_cast<const float4*>(&A[(long long)(aRow + 64) * lda + k0 + aCol]);
            pb0 = *reinterpret_cast<const float4*>(&B[(long long)(k0 + bRow) * ldb + bCol]);
            pb1 = *reinterpret_cast<const float4*>(&B[(long long)(k0 + bRow + 8) * ldb + bCol]);
        }

        #pragma unroll
        for (int kk = 0; kk < 16; kk += 8) {
            uint32_t af[4][4], bf[4][2];
            #pragma unroll
            for (int mt = 0; mt < 4; ++mt) {
                const int m = warpM + mt * 16;
                af[mt][0] = As[buf][kk + tg][m + g];
                af[mt][1] = As[buf][kk + tg][m + g + 8];
                af[mt][2] = As[buf][kk + tg + 4][m + g];
                af[mt][3] = As[buf][kk + tg + 4][m + g + 8];
            }
            #pragma unroll
            for (int nt = 0; nt < 4; ++nt) {
                const int n = warpN + nt * 8;
                bf[nt][0] = Bs[buf][kk + tg][n + g];
                bf[nt][1] = Bs[buf][kk + tg + 4][n + g];
            }
            #pragma unroll
            for (int mt = 0; mt < 4; ++mt)
                #pragma unroll
                for (int nt = 0; nt < 4; ++nt)
                    mma_tf32(acc[mt][nt], af[mt], bf[nt]);
        }

        if (kt + 1 < KT) {
            const int nb = 1 - buf;
            As[nb][aCol + 0][aRow] = f2tf32(pa0.x);
            As[nb][aCol + 1][aRow] = f2tf32(pa0.y);
            As[nb][aCol + 2][aRow] = f2tf32(pa0.z);
            As[nb][aCol + 3][aRow] = f2tf32(pa0.w);
            As[nb][aCol + 0][aRow + 64] = f2tf32(pa1.x);
            As[nb][aCol + 1][aRow + 64] = f2tf32(pa1.y);
            As[nb][aCol + 2][aRow + 64] = f2tf32(pa1.z);
            As[nb][aCol + 3][aRow + 64] = f2tf32(pa1.w);
            uint4 u0 = { f2tf32(pb0.x), f2tf32(pb0.y), f2tf32(pb0.z), f2tf32(pb0.w) };
            uint4 u1 = { f2tf32(pb1.x), f2tf32(pb1.y), f2tf32(pb1.z), f2tf32(pb1.w) };
            *(uint4*)&Bs[nb][bRow][bCol] = u0;
            *(uint4*)&Bs[nb][bRow + 8][bCol] = u1;
            __syncthreads();
        }
    }

    #pragma unroll
    for (int mt = 0; mt < 4; ++mt) {
        const int r0 = warpM + mt * 16 + g;
        #pragma unroll
        for (int nt = 0; nt < 4; ++nt) {
            const int c0 = warpN + nt * 8 + 2 * tg;
            float bx0 = 0.f, bx1 = 0.f;
            if (bias) {
                const int gcol = blockIdx.x * 128 + c0;
                bx0 = bias[gcol];
                bx1 = bias[gcol + 1];
            }
            float2 lo = { alpha * acc[mt][nt][0] + bx0, alpha * acc[mt][nt][1] + bx1 };
            float2 hi = { alpha * acc[mt][nt][2] + bx0, alpha * acc[mt][nt][3] + bx1 };
            *reinterpret_cast<float2*>(&C[(long long)r0 * ldc + c0]) = lo;
            *reinterpret_cast<float2*>(&C[(long long)(r0 + 8) * ldc + c0]) = hi;
        }
    }
}

// ---------------------------------------------------------------------------
extern "C" void kernel_launch(void* const* d_in, const int* in_sizes, int n_in,
                              void* d_out, int out_size)
{
    const float* x      = (const float*)d_in[0];  // [4, 8192, 256]
    const float* w_qkv  = (const float*)d_in[1];  // [256, 1536]
    const float* w_out  = (const float*)d_in[2];  // [512, 256]
    const float* b_out  = (const float*)d_in[3];  // [256]
    float*       out    = (float*)d_out;          // [4, 8192, 256]

    float *part, *dots, *A2, *WfP, *Wf;
    cudaGetSymbolAddress((void**)&part, g_part);
    cudaGetSymbolAddress((void**)&dots, g_dots);
    cudaGetSymbolAddress((void**)&A2,   g_A2);
    cudaGetSymbolAddress((void**)&WfP,  g_WfP);
    cudaGetSymbolAddress((void**)&Wf,   g_Wf);

    cudaFuncSetAttribute(fused_kv_dots,
                         cudaFuncAttributeMaxDynamicSharedMemorySize, FUSED_SMEM);

    // 1) fused: k/v projection + instance norm + partial dots
    fused_kv_dots<<<dim3(NCH, 32), 256, FUSED_SMEM>>>(x, w_qkv, part);

    // 2) deterministic chunk reduction
    reduce_dots<<<dim3(32, 4), 256>>>(part, dots);

    // 3) A2 = blockdiag(dots) @ w_out ; Wf[b] = w_q @ A2[b] / n (split-K)
    dots_wout<<<dim3(32, 8), 256>>>(dots, w_out, A2);
    wf_gemm_splitk<<<dim3(4, 4, BATCH * KSEG), 256>>>(w_qkv, A2, WfP);
    wf_reduce<<<(BATCH * DIM * DIM) / 256, 256>>>(WfP, Wf);

    // 4) out[b] = x[b] @ Wf[b] + b_out  (tf32 TC)
    gemm_tf32<<<dim3(DIM / 128, NTOK / 128, BATCH), 256>>>(
        x, DIM, (long long)NTOK * DIM,
        Wf, DIM, (long long)DIM * DIM,
        out, DIM, (long long)NTOK * DIM,
        DIM, b_out, 1.0f);
}